// round 6
// baseline (speedup 1.0000x reference)
#include <cuda_runtime.h>
#include <cuda_bf16.h>
#include <math.h>
#include <stddef.h>
#include <stdint.h>

// Problem constants
#define NHEAD 16
#define HDIM  64
#define SEQ   2048
#define BATCH 2
#define EMB   1024
#define MTOT  (BATCH * SEQ)   // 4096

// Scratch (device globals: allocation-free, graph-capturable)
__device__ float g_q[BATCH * NHEAD * SEQ * HDIM];
__device__ float g_k[BATCH * NHEAD * SEQ * HDIM];
__device__ float g_v[BATCH * NHEAD * SEQ * HDIM];
__device__ __nv_bfloat16 g_xh[MTOT * EMB], g_xl[MTOT * EMB];
__device__ __nv_bfloat16 g_wh[4 * EMB * EMB], g_wl[4 * EMB * EMB];
__device__ __nv_bfloat16 g_oh[MTOT * EMB], g_ol[MTOT * EMB];

// ===========================================================================
// mma.sync helpers (arch-portable tensor core path; works at compute_103)
// ===========================================================================
__device__ __forceinline__ void mma_bf16(float* d, const uint32_t* a, const uint32_t* b) {
    asm volatile(
        "mma.sync.aligned.m16n8k16.row.col.f32.bf16.bf16.f32 "
        "{%0,%1,%2,%3}, {%4,%5,%6,%7}, {%8,%9}, {%0,%1,%2,%3};"
        : "+f"(d[0]), "+f"(d[1]), "+f"(d[2]), "+f"(d[3])
        : "r"(a[0]), "r"(a[1]), "r"(a[2]), "r"(a[3]), "r"(b[0]), "r"(b[1]));
}

__device__ __forceinline__ void ldsm4(uint32_t* r, uint32_t addr) {
    asm volatile("ldmatrix.sync.aligned.m8n8.x4.shared.b16 {%0,%1,%2,%3}, [%4];"
        : "=r"(r[0]), "=r"(r[1]), "=r"(r[2]), "=r"(r[3]) : "r"(addr));
}

__device__ __forceinline__ void ldsm4t(uint32_t* r, uint32_t addr) {
    asm volatile("ldmatrix.sync.aligned.m8n8.x4.trans.shared.b16 {%0,%1,%2,%3}, [%4];"
        : "=r"(r[0]), "=r"(r[1]), "=r"(r[2]), "=r"(r[3]) : "r"(addr));
}

__device__ __forceinline__ uint32_t smem_u32(const void* p) {
    uint32_t a;
    asm("{ .reg .u64 t; cvta.to.shared.u64 t, %1; cvt.u32.u64 %0, t; }"
        : "=r"(a) : "l"(p));
    return a;
}

// hi/lo bf16 split of 2 floats (packed into u32 each)
__device__ __forceinline__ void split2(float x, float y, uint32_t& hi, uint32_t& lo) {
    __nv_bfloat162 h = __floats2bfloat162_rn(x, y);
    float hx = __bfloat162float(h.x), hy = __bfloat162float(h.y);
    __nv_bfloat162 l = __floats2bfloat162_rn(x - hx, y - hy);
    hi = *(uint32_t*)&h;
    lo = *(uint32_t*)&l;
}

// ===========================================================================
// Pre-split: f32 array -> bf16 hi/lo arrays (grid-stride over float4)
// ===========================================================================
__global__ __launch_bounds__(256) void split_kernel(
    const float* __restrict__ in, __nv_bfloat16* __restrict__ hi,
    __nv_bfloat16* __restrict__ lo, int n4)
{
    const int i = blockIdx.x * blockDim.x + threadIdx.x;
    if (i < n4) {
        const float4 v = *(const float4*)(in + (size_t)i * 4);
        uint32_t h0, l0, h1, l1;
        split2(v.x, v.y, h0, l0);
        split2(v.z, v.w, h1, l1);
        *(uint2*)(hi + (size_t)i * 4) = make_uint2(h0, h1);
        *(uint2*)(lo + (size_t)i * 4) = make_uint2(l0, l1);
    }
}

// ===========================================================================
// Tensor-core GEMM v2 (pre-split operands):
// C[M,N] = (Ah+Al)[M,K] @ (Bh+Bl)[N,K]^T + bias, 3-term split.
// CTA 128x128, BK=32, 8 warps (4x2). Hot loop: LDG.128 bf16 -> STS.128 ->
// LDSM -> HMMA only (no conversion). 80B smem row stride (16B-aligned,
// conflict-free LDSM).
// ===========================================================================
#define GBK 32
#define SROWB 80
#define SROWW (SROWB / 4)
#define TILE_U32 (128 * SROWW)

__global__ __launch_bounds__(256, 1) void gemm_tc2(
    const __nv_bfloat16* __restrict__ Ahg, const __nv_bfloat16* __restrict__ Alg,
    const __nv_bfloat16* __restrict__ Bhg, const __nv_bfloat16* __restrict__ Blg,
    const float* __restrict__ bias, float* __restrict__ C, int writeQKV)
{
    __shared__ uint32_t sh[4 * TILE_U32];   // 40960 B: Ah, Al, Bh, Bl
    uint32_t* AhS = sh;
    uint32_t* AlS = sh + TILE_U32;
    uint32_t* BhS = sh + 2 * TILE_U32;
    uint32_t* BlS = sh + 3 * TILE_U32;

    const int tid = threadIdx.x;
    const int lane = tid & 31;
    const int wid = tid >> 5;
    const int wm = wid & 3;
    const int wn = wid >> 2;
    const int m0 = blockIdx.y * 128;
    const int n0 = blockIdx.x * 128;

    // gmem staging: per buffer, thread copies 2x 16B (8 bf16) chunks
    const int lrow = tid >> 2;          // 0..63 (and +64)
    const int c16 = tid & 3;            // 16B chunk within 64B row-chunk

    const int mat = lane >> 3, lr8 = lane & 7;
    const uint32_t sbase = smem_u32(sh);
    const uint32_t a_off = (uint32_t)((wm * 32 + (mat & 1) * 8 + lr8) * SROWB + (mat >> 1) * 16);
    const uint32_t b_off = (uint32_t)((wn * 64 + (mat >> 1) * 8 + lr8) * SROWB + (mat & 1) * 16);

    const uint32_t sAh = sbase + a_off;
    const uint32_t sAl = sAh + TILE_U32 * 4;
    const uint32_t sBh = sbase + 2 * TILE_U32 * 4 + b_off;
    const uint32_t sBl = sBh + TILE_U32 * 4;

    float acc[2][8][4];
#pragma unroll
    for (int mf = 0; mf < 2; mf++)
#pragma unroll
        for (int nf = 0; nf < 8; nf++)
#pragma unroll
            for (int e = 0; e < 4; e++) acc[mf][nf][e] = 0.f;

    const __nv_bfloat16* Ahp = Ahg + (size_t)m0 * EMB;
    const __nv_bfloat16* Alp = Alg + (size_t)m0 * EMB;
    const __nv_bfloat16* Bhp = Bhg + (size_t)n0 * EMB;
    const __nv_bfloat16* Blp = Blg + (size_t)n0 * EMB;

    uint4 ahr[2], alr[2], bhr[2], blr[2];
#pragma unroll
    for (int it = 0; it < 2; it++) {
        const size_t g = (size_t)(lrow + it * 64) * EMB + c16 * 8;
        ahr[it] = *(const uint4*)(Ahp + g);
        alr[it] = *(const uint4*)(Alp + g);
        bhr[it] = *(const uint4*)(Bhp + g);
        blr[it] = *(const uint4*)(Blp + g);
    }

    for (int kk = 0; kk < EMB / GBK; kk++) {
        __syncthreads();
#pragma unroll
        for (int it = 0; it < 2; it++) {
            const int w0 = (lrow + it * 64) * SROWW + c16 * 4;
            *(uint4*)(AhS + w0) = ahr[it];
            *(uint4*)(AlS + w0) = alr[it];
            *(uint4*)(BhS + w0) = bhr[it];
            *(uint4*)(BlS + w0) = blr[it];
        }
        __syncthreads();

        if (kk + 1 < EMB / GBK) {
            const int kcol = (kk + 1) * GBK + c16 * 8;
#pragma unroll
            for (int it = 0; it < 2; it++) {
                const size_t g = (size_t)(lrow + it * 64) * EMB + kcol;
                ahr[it] = *(const uint4*)(Ahp + g);
                alr[it] = *(const uint4*)(Alp + g);
                bhr[it] = *(const uint4*)(Bhp + g);
                blr[it] = *(const uint4*)(Blp + g);
            }
        }

#pragma unroll
        for (int ks = 0; ks < 2; ks++) {
            const uint32_t kadd = ks * 32;
            uint32_t ah[2][4], al[2][4], bh[4][4], bl[4][4];
#pragma unroll
            for (int mf = 0; mf < 2; mf++) {
                ldsm4(ah[mf], sAh + mf * 16 * SROWB + kadd);
                ldsm4(al[mf], sAl + mf * 16 * SROWB + kadd);
            }
#pragma unroll
            for (int np = 0; np < 4; np++) {
                ldsm4(bh[np], sBh + np * 16 * SROWB + kadd);
                ldsm4(bl[np], sBl + np * 16 * SROWB + kadd);
            }
#pragma unroll
            for (int mf = 0; mf < 2; mf++)
#pragma unroll
                for (int nf = 0; nf < 8; nf++) {
                    const int np = nf >> 1;
                    uint32_t* bhp = &bh[np][(nf & 1) * 2];
                    uint32_t* blp = &bl[np][(nf & 1) * 2];
                    mma_bf16(acc[mf][nf], ah[mf], bhp);
                    mma_bf16(acc[mf][nf], ah[mf], blp);
                    mma_bf16(acc[mf][nf], al[mf], bhp);
                }
        }
    }

#pragma unroll
    for (int mf = 0; mf < 2; mf++) {
#pragma unroll
        for (int half = 0; half < 2; half++) {
            const int m = m0 + wm * 32 + mf * 16 + (lane >> 2) + half * 8;
            const int b = m >> 11;
            const int s = m & (SEQ - 1);
#pragma unroll
            for (int nf = 0; nf < 8; nf++) {
                const int n = n0 + wn * 64 + nf * 8 + ((lane & 3) << 1);
                float2 v;
                v.x = acc[mf][nf][half * 2 + 0] + bias[n];
                v.y = acc[mf][nf][half * 2 + 1] + bias[n + 1];
                if (writeQKV) {
                    const int h = n >> 6;
                    const int d = n & 63;
                    *(float2*)(C + (((size_t)(b * NHEAD + h)) * SEQ + s) * HDIM + d) = v;
                } else {
                    *(float2*)(C + (size_t)m * EMB + n) = v;
                }
            }
        }
    }
}

// ===========================================================================
// Tensor-core causal flash attention (unchanged core; epilogue now emits
// hi/lo bf16 directly for the output-projection GEMM).
// ===========================================================================
#define QT 128
#define KT 64
#define AROWW 36            // u32 words per smem row (144 B)
#define ABUF (64 * AROWW)   // words per 64-row buffer

__global__ __launch_bounds__(256) void attn_tc(
    const float* __restrict__ Q, const float* __restrict__ K,
    const float* __restrict__ V,
    __nv_bfloat16* __restrict__ Oh, __nv_bfloat16* __restrict__ Ol)
{
    __shared__ uint32_t sm[4 * ABUF];   // 36864 B
    const int tid = threadIdx.x;
    const int lane = tid & 31;
    const int wid = tid >> 5;
    const int lr8 = lane & 7;
    const int mat = lane >> 3;
    const int qb = blockIdx.x;
    const int bh = blockIdx.y;

    const uint32_t sbase = smem_u32(sm);

    const float* Qg = Q + ((size_t)bh * SEQ + (size_t)qb * QT) * HDIM;
    const float* Kg = K + (size_t)bh * SEQ * HDIM;
    const float* Vg = V + (size_t)bh * SEQ * HDIM;

    const int r16 = tid >> 4;
    const int c4f = (tid & 15) << 2;
    const int kw  = (tid & 15) << 1;

    // ---- stage Q (x 1/8), split hi/lo into smem, ldsm into registers ----
#pragma unroll
    for (int u = 0; u < 8; u++) {
        const int row = r16 + u * 16;
        const float4 q = *(const float4*)(Qg + (size_t)row * HDIM + c4f);
        uint32_t h0, l0, h1, l1;
        split2(q.x * 0.125f, q.y * 0.125f, h0, l0);
        split2(q.z * 0.125f, q.w * 0.125f, h1, l1);
        const int w = row * AROWW + kw;
        *(uint2*)(sm + w) = make_uint2(h0, h1);
        *(uint2*)(sm + 2 * ABUF + w) = make_uint2(l0, l1);
    }
    __syncthreads();

    uint32_t qh[4][4], ql[4][4];
    {
        const uint32_t qa = sbase +
            (uint32_t)((wid * 16 + (mat & 1) * 8 + lr8) * 144 + (mat >> 1) * 16);
#pragma unroll
        for (int ks = 0; ks < 4; ks++) {
            ldsm4(qh[ks], qa + ks * 32);
            ldsm4(ql[ks], qa + 2 * ABUF * 4 + ks * 32);
        }
    }

    float oacc[8][4];
#pragma unroll
    for (int nf = 0; nf < 8; nf++)
#pragma unroll
        for (int e = 0; e < 4; e++) oacc[nf][e] = 0.f;
    float m0r = -INFINITY, m1r = -INFINITY, l0r = 0.f, l1r = 0.f;

    const int jbmax = 2 * qb + 1;
    const int qrow0 = qb * QT + wid * 16 + (lane >> 2);

    float4 kreg[4];
#pragma unroll
    for (int u = 0; u < 4; u++)
        kreg[u] = *(const float4*)(Kg + (size_t)(r16 + u * 16) * HDIM + c4f);

    for (int jb = 0; jb <= jbmax; jb++) {
        __syncthreads();
#pragma unroll
        for (int u = 0; u < 4; u++) {
            uint32_t h0, l0, h1, l1;
            split2(kreg[u].x, kreg[u].y, h0, l0);
            split2(kreg[u].z, kreg[u].w, h1, l1);
            const int w = (r16 + u * 16) * AROWW + kw;
            *(uint2*)(sm + w) = make_uint2(h0, h1);
            *(uint2*)(sm + ABUF + w) = make_uint2(l0, l1);
        }
        __syncthreads();

        float4 vreg[4];
        {
            const float* Vt = Vg + (size_t)jb * KT * HDIM;
#pragma unroll
            for (int u = 0; u < 4; u++)
                vreg[u] = *(const float4*)(Vt + (size_t)(r16 + u * 16) * HDIM + c4f);
        }

        float sacc[8][4];
#pragma unroll
        for (int nf = 0; nf < 8; nf++)
#pragma unroll
            for (int e = 0; e < 4; e++) sacc[nf][e] = 0.f;

#pragma unroll
        for (int ks = 0; ks < 4; ks++) {
#pragma unroll
            for (int np = 0; np < 4; np++) {
                uint32_t kh[4], kl[4];
                const uint32_t ka = sbase +
                    (uint32_t)((np * 16 + (mat >> 1) * 8 + lr8) * 144 + ks * 32 + (mat & 1) * 16);
                ldsm4(kh, ka);
                ldsm4(kl, ka + ABUF * 4);
#pragma unroll
                for (int hh = 0; hh < 2; hh++) {
                    float* d = sacc[np * 2 + hh];
                    mma_bf16(d, qh[ks], &kh[hh * 2]);
                    mma_bf16(d, qh[ks], &kl[hh * 2]);
                    mma_bf16(d, ql[ks], &kh[hh * 2]);
                }
            }
        }

#pragma unroll
        for (int u = 0; u < 4; u++) {
            uint32_t h0, l0, h1, l1;
            split2(vreg[u].x, vreg[u].y, h0, l0);
            split2(vreg[u].z, vreg[u].w, h1, l1);
            const int w = (r16 + u * 16) * AROWW + kw;
            *(uint2*)(sm + 2 * ABUF + w) = make_uint2(h0, h1);
            *(uint2*)(sm + 3 * ABUF + w) = make_uint2(l0, l1);
        }
        __syncthreads();

        if (jb < jbmax) {
            const float* Kt = Kg + (size_t)(jb + 1) * KT * HDIM;
#pragma unroll
            for (int u = 0; u < 4; u++)
                kreg[u] = *(const float4*)(Kt + (size_t)(r16 + u * 16) * HDIM + c4f);
        }

        if (jb * KT + KT - 1 > qrow0) {
#pragma unroll
            for (int nt = 0; nt < 8; nt++) {
                const int c = jb * KT + nt * 8 + ((lane & 3) << 1);
                if (c     > qrow0)     sacc[nt][0] = -INFINITY;
                if (c + 1 > qrow0)     sacc[nt][1] = -INFINITY;
                if (c     > qrow0 + 8) sacc[nt][2] = -INFINITY;
                if (c + 1 > qrow0 + 8) sacc[nt][3] = -INFINITY;
            }
        }

        float mx0 = sacc[0][0], mx1 = sacc[0][2];
#pragma unroll
        for (int nt = 0; nt < 8; nt++) {
            mx0 = fmaxf(mx0, fmaxf(sacc[nt][0], sacc[nt][1]));
            mx1 = fmaxf(mx1, fmaxf(sacc[nt][2], sacc[nt][3]));
        }
        mx0 = fmaxf(mx0, __shfl_xor_sync(~0u, mx0, 1));
        mx0 = fmaxf(mx0, __shfl_xor_sync(~0u, mx0, 2));
        mx1 = fmaxf(mx1, __shfl_xor_sync(~0u, mx1, 1));
        mx1 = fmaxf(mx1, __shfl_xor_sync(~0u, mx1, 2));
        const float mn0 = fmaxf(m0r, mx0), mn1 = fmaxf(m1r, mx1);
        const float cr0 = __expf(m0r - mn0), cr1 = __expf(m1r - mn1);
        m0r = mn0; m1r = mn1;
        float rs0 = 0.f, rs1 = 0.f;
#pragma unroll
        for (int nt = 0; nt < 8; nt++) {
            sacc[nt][0] = __expf(sacc[nt][0] - mn0);
            sacc[nt][1] = __expf(sacc[nt][1] - mn0);
            sacc[nt][2] = __expf(sacc[nt][2] - mn1);
            sacc[nt][3] = __expf(sacc[nt][3] - mn1);
            rs0 += sacc[nt][0] + sacc[nt][1];
            rs1 += sacc[nt][2] + sacc[nt][3];
        }
        rs0 += __shfl_xor_sync(~0u, rs0, 1);
        rs0 += __shfl_xor_sync(~0u, rs0, 2);
        rs1 += __shfl_xor_sync(~0u, rs1, 1);
        rs1 += __shfl_xor_sync(~0u, rs1, 2);
        l0r = l0r * cr0 + rs0;
        l1r = l1r * cr1 + rs1;
#pragma unroll
        for (int nf = 0; nf < 8; nf++) {
            oacc[nf][0] *= cr0; oacc[nf][1] *= cr0;
            oacc[nf][2] *= cr1; oacc[nf][3] *= cr1;
        }

#pragma unroll
        for (int ks = 0; ks < 4; ks++) {
            uint32_t ph[4], pl[4];
            split2(sacc[2 * ks][0],     sacc[2 * ks][1],     ph[0], pl[0]);
            split2(sacc[2 * ks][2],     sacc[2 * ks][3],     ph[1], pl[1]);
            split2(sacc[2 * ks + 1][0], sacc[2 * ks + 1][1], ph[2], pl[2]);
            split2(sacc[2 * ks + 1][2], sacc[2 * ks + 1][3], ph[3], pl[3]);
#pragma unroll
            for (int np = 0; np < 4; np++) {
                uint32_t vh[4], vl[4];
                const uint32_t va = sbase + (uint32_t)(2 * ABUF * 4) +
                    (uint32_t)((ks * 16 + (mat & 1) * 8 + lr8) * 144 + np * 32 + (mat >> 1) * 16);
                ldsm4t(vh, va);
                ldsm4t(vl, va + ABUF * 4);
#pragma unroll
                for (int hh = 0; hh < 2; hh++) {
                    float* d = oacc[np * 2 + hh];
                    mma_bf16(d, ph, &vh[hh * 2]);
                    mma_bf16(d, ph, &vl[hh * 2]);
                    mma_bf16(d, pl, &vh[hh * 2]);
                }
            }
        }
    }

    // epilogue: normalize + hi/lo split, write bf16 [b, s, h*64 + d]
    const int b = bh >> 4, h = bh & 15;
    const float inv0 = 1.f / l0r, inv1 = 1.f / l1r;
#pragma unroll
    for (int nt = 0; nt < 8; nt++) {
        const int col = h * HDIM + nt * 8 + ((lane & 3) << 1);
        const size_t o0 = ((size_t)(b * SEQ) + qrow0) * EMB + col;
        const size_t o1 = ((size_t)(b * SEQ) + qrow0 + 8) * EMB + col;
        uint32_t h0, l0;
        split2(oacc[nt][0] * inv0, oacc[nt][1] * inv0, h0, l0);
        *(uint32_t*)(Oh + o0) = h0;
        *(uint32_t*)(Ol + o0) = l0;
        split2(oacc[nt][2] * inv1, oacc[nt][3] * inv1, h0, l0);
        *(uint32_t*)(Oh + o1) = h0;
        *(uint32_t*)(Ol + o1) = l0;
    }
}

// ---------------------------------------------------------------------------
extern "C" void kernel_launch(void* const* d_in, const int* in_sizes, int n_in,
                              void* d_out, int out_size)
{
    (void)in_sizes; (void)n_in; (void)out_size;
    const float* x  = (const float*)d_in[0];
    // d_in[1] = mask (causal tril, implied — unused)
    const float* Wq = (const float*)d_in[2];
    const float* bq = (const float*)d_in[3];
    const float* Wk = (const float*)d_in[4];
    const float* bk = (const float*)d_in[5];
    const float* Wv = (const float*)d_in[6];
    const float* bv = (const float*)d_in[7];
    const float* Wo = (const float*)d_in[8];
    const float* bo = (const float*)d_in[9];
    float* out = (float*)d_out;

    float *gq, *gk, *gv;
    __nv_bfloat16 *xh, *xl, *wh, *wl, *oh, *ol;
    cudaGetSymbolAddress((void**)&gq, g_q);
    cudaGetSymbolAddress((void**)&gk, g_k);
    cudaGetSymbolAddress((void**)&gv, g_v);
    cudaGetSymbolAddress((void**)&xh, g_xh);
    cudaGetSymbolAddress((void**)&xl, g_xl);
    cudaGetSymbolAddress((void**)&wh, g_wh);
    cudaGetSymbolAddress((void**)&wl, g_wl);
    cudaGetSymbolAddress((void**)&oh, g_oh);
    cudaGetSymbolAddress((void**)&ol, g_ol);

    const int WN = EMB * EMB;   // 1M elements per weight

    // Pre-split activations and weights into bf16 hi/lo
    split_kernel<<<(MTOT * EMB / 4) / 256, 256>>>(x, xh, xl, MTOT * EMB / 4);
    split_kernel<<<(WN / 4) / 256, 256>>>(Wq, wh + 0 * WN, wl + 0 * WN, WN / 4);
    split_kernel<<<(WN / 4) / 256, 256>>>(Wk, wh + 1 * WN, wl + 1 * WN, WN / 4);
    split_kernel<<<(WN / 4) / 256, 256>>>(Wv, wh + 2 * WN, wl + 2 * WN, WN / 4);
    split_kernel<<<(WN / 4) / 256, 256>>>(Wo, wh + 3 * WN, wl + 3 * WN, WN / 4);

    const dim3 gemm_grid(EMB / 128, MTOT / 128);  // (8, 32)
    gemm_tc2<<<gemm_grid, 256>>>(xh, xl, wh + 0 * WN, wl + 0 * WN, bq, gq, 1);
    gemm_tc2<<<gemm_grid, 256>>>(xh, xl, wh + 1 * WN, wl + 1 * WN, bk, gk, 1);
    gemm_tc2<<<gemm_grid, 256>>>(xh, xl, wh + 2 * WN, wl + 2 * WN, bv, gv, 1);

    const dim3 attn_grid(SEQ / QT, BATCH * NHEAD);  // (16, 32)
    attn_tc<<<attn_grid, 256>>>(gq, gk, gv, oh, ol);

    gemm_tc2<<<gemm_grid, 256>>>(oh, ol, wh + 3 * WN, wl + 3 * WN, bo, out, 0);
}